// round 16
// baseline (speedup 1.0000x reference)
#include <cuda_runtime.h>
#include <cuda_fp16.h>
#include <math.h>
#include <stdint.h>

// ---------------- problem constants -----------------------------------------
#define TOKENS 4096
#define DDIM   1024
#define FDIM   4096
#define NEXP   8
#define PAIRS  (TOKENS * 2)
#define CAP    TOKENS

// ---------------- GEMM tiling ------------------------------------------------
#define BM 128
#define BN 128
#define BK 32
#define NTH 256                    // 8 warps, 2(m) x 4(n), warp tile 64x32
#define A_BYTES  (BM * 80)         // 10240 (LDT=40 halves, 80B rows)
#define B_BYTES  (BN * 80)         // 10240
#define SOFF_STAGE 1024
#define SOFF_B (SOFF_STAGE + 3 * A_BYTES)
#define SMEM_BYTES (SOFF_STAGE + 3 * A_BYTES + 3 * B_BYTES)   // 62464
#define LDTT 136                   // epilogue transpose stride (halves)

// ---------------- scratch (72 MB — proven budget) -------------------------------
__device__ int    g_counts[NEXP];
__device__ int    g_list[NEXP * CAP];
__device__ float  g_prob[PAIRS];
__device__ __half g_xf[(size_t)TOKENS * DDIM];   // fp16 x  (8 MB)
__device__ __half g_hf[(size_t)PAIRS * FDIM];    // fp16 h  (64 MB)

// ---------------- ptx helpers --------------------------------------------------
__device__ __forceinline__ uint32_t smem_u32(const void* p) {
    uint32_t a;
    asm("{ .reg .u64 t; cvta.to.shared.u64 t, %1; cvt.u32.u64 %0, t; }"
        : "=r"(a) : "l"(p));
    return a;
}
__device__ __forceinline__ void cp16(uint32_t dst, const void* src) {
    asm volatile("cp.async.cg.shared.global [%0], [%1], 16;" :: "r"(dst), "l"(src));
}
__device__ __forceinline__ void cp_commit() {
    asm volatile("cp.async.commit_group;" ::: "memory");
}
template <int N>
__device__ __forceinline__ void cp_wait() {
    asm volatile("cp.async.wait_group %0;" :: "n"(N) : "memory");
}
__device__ __forceinline__ void ldm4(uint32_t* r, uint32_t a) {
    asm volatile("ldmatrix.sync.aligned.m8n8.x4.shared.b16 {%0,%1,%2,%3}, [%4];"
                 : "=r"(r[0]), "=r"(r[1]), "=r"(r[2]), "=r"(r[3]) : "r"(a));
}
__device__ __forceinline__ void mma_f16(float* c, const uint32_t* a, const uint32_t* b) {
    asm volatile(
        "mma.sync.aligned.m16n8k16.row.col.f32.f16.f16.f32 "
        "{%0,%1,%2,%3}, {%4,%5,%6,%7}, {%8,%9}, {%0,%1,%2,%3};"
        : "+f"(c[0]), "+f"(c[1]), "+f"(c[2]), "+f"(c[3])
        : "r"(a[0]), "r"(a[1]), "r"(a[2]), "r"(a[3]), "r"(b[0]), "r"(b[1]));
}

// ---------------- math helpers --------------------------------------------------
__device__ __forceinline__ float gelu_tanh(float v) {
    const float c = 0.7978845608028654f;
    float u = c * (v + 0.044715f * v * v * v);
    return 0.5f * v * (1.0f + tanhf(u));
}
__device__ __forceinline__ void conv_sts(char* smem, uint32_t off, float4 v) {
    __half2 h0 = __halves2half2(__float2half_rn(v.x), __float2half_rn(v.y));
    __half2 h1 = __halves2half2(__float2half_rn(v.z), __float2half_rn(v.w));
    *reinterpret_cast<uint2*>(smem + off) =
        make_uint2(*(uint32_t*)&h0, *(uint32_t*)&h1);
}

// ---------------- kernel 0: zero output + counts --------------------------------
__global__ void zero_kernel(float* __restrict__ out, int n) {
    int i = blockIdx.x * blockDim.x + threadIdx.x;
    if (i < n) out[i] = 0.0f;
    if (blockIdx.x == 0 && threadIdx.x < NEXP) g_counts[threadIdx.x] = 0;
}

// ---------------- kernel: gate + x->fp16 convert (fused) -------------------------
__global__ __launch_bounds__(256) void gate_kernel(
    const float* __restrict__ x, const float* __restrict__ gw)
{
    int t = blockIdx.x;
    const float* xr = x + (size_t)t * DDIM;

    float acc[NEXP];
#pragma unroll
    for (int e = 0; e < NEXP; e++) acc[e] = 0.0f;
    for (int d = threadIdx.x; d < DDIM; d += 256) {
        float xv = xr[d];
        g_xf[(size_t)t * DDIM + d] = __float2half_rn(xv);
#pragma unroll
        for (int e = 0; e < NEXP; e++) acc[e] += xv * gw[e * DDIM + d];
    }
#pragma unroll
    for (int e = 0; e < NEXP; e++) {
#pragma unroll
        for (int o = 16; o > 0; o >>= 1)
            acc[e] += __shfl_xor_sync(0xffffffff, acc[e], o);
    }
    __shared__ float red[NEXP][8];
    int warp = threadIdx.x >> 5, lane = threadIdx.x & 31;
    if (lane == 0) {
#pragma unroll
        for (int e = 0; e < NEXP; e++) red[e][warp] = acc[e];
    }
    __syncthreads();
    if (threadIdx.x == 0) {
        float lg[NEXP];
#pragma unroll
        for (int e = 0; e < NEXP; e++) {
            float s = 0.0f;
#pragma unroll
            for (int w = 0; w < 8; w++) s += red[e][w];
            lg[e] = s;
        }
        float mx = lg[0];
#pragma unroll
        for (int e = 1; e < NEXP; e++) mx = fmaxf(mx, lg[e]);
        float pe[NEXP], s = 0.0f;
#pragma unroll
        for (int e = 0; e < NEXP; e++) { pe[e] = expf(lg[e] - mx); s += pe[e]; }
        float inv = 1.0f / s;
        int i0 = 0;
#pragma unroll
        for (int e = 1; e < NEXP; e++) if (pe[e] > pe[i0]) i0 = e;
        int i1 = (i0 == 0) ? 1 : 0;
#pragma unroll
        for (int e = 0; e < NEXP; e++)
            if (e != i0 && pe[e] > pe[i1]) i1 = e;
        int p0 = t * 2, p1 = t * 2 + 1;
        g_prob[p0] = pe[i0] * inv;
        g_prob[p1] = pe[i1] * inv;
        int pos0 = atomicAdd(&g_counts[i0], 1);
        g_list[i0 * CAP + pos0] = p0;
        int pos1 = atomicAdd(&g_counts[i1], 1);
        g_list[i1 * CAP + pos1] = p1;
    }
}

// ---------------- grouped fp16 GEMM (R15 + coalesced L1 epilogue) ----------------
template <int KDIM, bool L2TAG>
__global__ __launch_bounds__(NTH, 2)
void moe_fp16(const float* __restrict__ W,
              const float* __restrict__ bias,
              float* __restrict__ dout)
{
    constexpr int KSPLIT = L2TAG ? 2 : 1;
    constexpr int KLOC = KDIM / KSPLIT;
    constexpr int NCH = KLOC / BK;

    int e   = blockIdx.z;
    int cnt = g_counts[e];
    int m0  = blockIdx.y * BM;
    if (m0 >= cnt) return;
    int ks    = blockIdx.x % KSPLIT;
    int n0    = (blockIdx.x / KSPLIT) * BN;
    int kbase = ks * KLOC;

    extern __shared__ __align__(128) char smem[];
    uint32_t sb = smem_u32(smem);
    int* rows = (int*)smem;

    int tid = threadIdx.x, wid = tid >> 5, lane = tid & 31;

    if (tid < BM) {
        int m = m0 + tid;
        rows[tid] = g_list[e * CAP + (m < cnt ? m : m0)];
    }
    __syncthreads();

    // ---- A: cp.async mapping (2 threads/row, 32B each) ----
    int arow = tid >> 1;
    int pa = rows[arow];
    const __half* a_rowp = L2TAG ? (g_hf + (size_t)pa * KDIM)
                                 : (g_xf + (size_t)(pa >> 1) * KDIM);
    const char* a_src = (const char*)(a_rowp + kbase) + (tid & 1) * 32;
    uint32_t a_dst = sb + SOFF_STAGE + (uint32_t)arow * 80 + (tid & 1) * 32;

    // ---- W: LDG float4 mapping (4 per thread) + STS offsets ----
    const float* wp[4];
    uint32_t woff[4];
#pragma unroll
    for (int j = 0; j < 4; j++) {
        int s = tid + j * 256;
        int r = s >> 3;
        int k4 = (s & 7) << 2;
        wp[j] = W + ((size_t)(n0 + r) * NEXP + e) * KDIM + kbase + k4;
        woff[j] = (uint32_t)r * 80 + (uint32_t)k4 * 2;
    }

    // ---- fragment addressing (validated R2/R5/R6/R8; LDT=40) ----
    int wm = wid & 1, wn = wid >> 1;
    int li = lane >> 3, lr = lane & 7;
    uint32_t aoff = (uint32_t)((wm * 64 + lr + (li & 1) * 8) * 80 + (li >> 1) * 16);
    uint32_t boff = (uint32_t)((wn * 32 + (li >> 1) * 8 + lr) * 80 + (li & 1) * 16);

    float acc[4][4][4];
#pragma unroll
    for (int im = 0; im < 4; im++)
#pragma unroll
        for (int in = 0; in < 4; in++)
#pragma unroll
            for (int q = 0; q < 4; q++) acc[im][in][q] = 0.0f;

    // ---- prologue ----
    cp16(a_dst, a_src);
    cp16(a_dst + 16, a_src + 16);
    cp_commit();
    cp16(a_dst + A_BYTES, a_src + BK * 2);
    cp16(a_dst + A_BYTES + 16, a_src + BK * 2 + 16);
    cp_commit();
    float4 wreg[4];
#pragma unroll
    for (int j = 0; j < 4; j++) wreg[j] = *(const float4*)(wp[j]);
    char* b0c = smem + SOFF_B;
#pragma unroll
    for (int j = 0; j < 4; j++) conv_sts(b0c, woff[j], wreg[j]);
#pragma unroll
    for (int j = 0; j < 4; j++) wreg[j] = *(const float4*)(wp[j] + BK);

    int sA = 0, sB = 0;        // both track i % 3
    for (int i = 0; i < NCH; i++) {
        cp_wait<1>();
        __syncthreads();

        if (i + 2 < NCH) {
            int s2 = sA + 2; if (s2 >= 3) s2 -= 3;
            uint32_t off = (uint32_t)s2 * A_BYTES;
            int kb = (i + 2) * BK * 2;
            cp16(a_dst + off, a_src + kb);
            cp16(a_dst + off + 16, a_src + kb + 16);
        }
        cp_commit();

        uint32_t As = sb + SOFF_STAGE + (uint32_t)sA * A_BYTES;
        uint32_t Bs = sb + SOFF_B + (uint32_t)sB * B_BYTES;

        uint32_t bf[2][4][2];
        {
            uint32_t t4[4];
            ldm4(t4, Bs + boff);
            bf[0][0][0] = t4[0]; bf[0][0][1] = t4[1];
            bf[0][1][0] = t4[2]; bf[0][1][1] = t4[3];
            ldm4(t4, Bs + boff + 1280);
            bf[0][2][0] = t4[0]; bf[0][2][1] = t4[1];
            bf[0][3][0] = t4[2]; bf[0][3][1] = t4[3];
        }

        if (i + 1 < NCH) {
            int s1 = sB + 1; if (s1 >= 3) s1 -= 3;
            char* bc = smem + SOFF_B + (size_t)s1 * B_BYTES;
#pragma unroll
            for (int j = 0; j < 4; j++) conv_sts(bc, woff[j], wreg[j]);
        }
        if (i + 2 < NCH) {
            int k0 = (i + 2) * BK;
#pragma unroll
            for (int j = 0; j < 4; j++) wreg[j] = *(const float4*)(wp[j] + k0);
        }

#pragma unroll
        for (int kk = 0; kk < BK; kk += 16) {
            int cur = (kk >> 4) & 1;
            if (kk + 16 < BK) {
                uint32_t t4[4];
                ldm4(t4, Bs + boff + (kk + 16) * 2);
                bf[cur ^ 1][0][0] = t4[0]; bf[cur ^ 1][0][1] = t4[1];
                bf[cur ^ 1][1][0] = t4[2]; bf[cur ^ 1][1][1] = t4[3];
                ldm4(t4, Bs + boff + 1280 + (kk + 16) * 2);
                bf[cur ^ 1][2][0] = t4[0]; bf[cur ^ 1][2][1] = t4[1];
                bf[cur ^ 1][3][0] = t4[2]; bf[cur ^ 1][3][1] = t4[3];
            }
#pragma unroll
            for (int im = 0; im < 4; im++) {
                uint32_t af[4];
                ldm4(af, As + aoff + im * 1280 + kk * 2);
#pragma unroll
                for (int in = 0; in < 4; in++)
                    mma_f16(acc[im][in], af, bf[cur][in]);
            }
        }
        if (++sA == 3) sA = 0;
        if (++sB == 3) sB = 0;
    }

    // ---- epilogue ----
    int qr = lane >> 2, qc = (lane & 3) * 2;
    if (!L2TAG) {
        // stage through smem for coalesced 256B-per-row writes of g_hf
        __syncthreads();                     // mainloop buffer reads done
        __half* T = (__half*)(smem + SOFF_STAGE);     // [128][LDTT]
        const float* bb = bias + (size_t)e * FDIM;
#pragma unroll
        for (int im = 0; im < 4; im++) {
#pragma unroll
            for (int half = 0; half < 2; half++) {
                int m_loc = wm * 64 + im * 16 + qr + half * 8;
#pragma unroll
                for (int in = 0; in < 4; in++) {
                    int col = wn * 32 + in * 8 + qc;
                    float v0 = acc[im][in][half * 2 + 0] + bb[n0 + col];
                    float v1 = acc[im][in][half * 2 + 1] + bb[n0 + col + 1];
                    __half2 hv = __halves2half2(__float2half_rn(gelu_tanh(v0)),
                                                __float2half_rn(gelu_tanh(v1)));
                    *reinterpret_cast<uint32_t*>(T + m_loc * LDTT + col) =
                        *(uint32_t*)&hv;
                }
            }
        }
        __syncthreads();
        // copy out: 2 threads/row, 128B each -> 256B contiguous per row
        int r  = tid >> 1;
        int hh = (tid & 1) * 64;             // half-row offset in halves
        if (m0 + r < cnt) {
            int p = rows[r];
            const uint4* srcp = (const uint4*)(T + r * LDTT + hh);
            uint4* dstp = (uint4*)(g_hf + (size_t)p * FDIM + n0 + hh);
#pragma unroll
            for (int j = 0; j < 8; j++) dstp[j] = srcp[j];
        }
    } else {
#pragma unroll
        for (int im = 0; im < 4; im++) {
#pragma unroll
            for (int half = 0; half < 2; half++) {
                int m_loc = wm * 64 + im * 16 + qr + half * 8;
                if (m0 + m_loc >= cnt) continue;
                int p = rows[m_loc];
                float pr = g_prob[p];
                float* op = dout + (size_t)(p >> 1) * DDIM;
                const float* bb = bias + (size_t)e * DDIM;
#pragma unroll
                for (int in = 0; in < 4; in++) {
                    int col = n0 + wn * 32 + in * 8 + qc;
                    float b0 = (ks == 0) ? bb[col] : 0.0f;
                    float b1 = (ks == 0) ? bb[col + 1] : 0.0f;
                    atomicAdd(&op[col],
                              pr * (acc[im][in][half * 2 + 0] + b0));
                    atomicAdd(&op[col + 1],
                              pr * (acc[im][in][half * 2 + 1] + b1));
                }
            }
        }
    }
}

// ---------------- launch --------------------------------------------------------------
extern "C" void kernel_launch(void* const* d_in, const int* in_sizes, int n_in,
                              void* d_out, int out_size)
{
    (void)in_sizes; (void)n_in; (void)out_size;
    const float* x  = (const float*)d_in[0];
    const float* gw = (const float*)d_in[1];
    const float* w1 = (const float*)d_in[2];
    const float* b1 = (const float*)d_in[3];
    const float* w2 = (const float*)d_in[4];
    const float* b2 = (const float*)d_in[5];
    float* out = (float*)d_out;

    cudaFuncSetAttribute(moe_fp16<DDIM, false>,
                         cudaFuncAttributeMaxDynamicSharedMemorySize, SMEM_BYTES);
    cudaFuncSetAttribute(moe_fp16<FDIM, true>,
                         cudaFuncAttributeMaxDynamicSharedMemorySize, SMEM_BYTES);

    zero_kernel<<<(TOKENS * DDIM + 255) / 256, 256>>>(out, TOKENS * DDIM);
    gate_kernel<<<TOKENS, 256>>>(x, gw);

    dim3 g1(FDIM / BN, TOKENS / BM, NEXP);        // 32 x 32 x 8
    moe_fp16<DDIM, false><<<g1, NTH, SMEM_BYTES>>>(w1, b1, nullptr);

    dim3 g2((DDIM / BN) * 2, TOKENS / BM, NEXP);  // 16 x 32 x 8, k-split
    moe_fp16<FDIM, true><<<g2, NTH, SMEM_BYTES>>>(w2, b2, out);
}

// round 17
// speedup vs baseline: 1.0135x; 1.0135x over previous
#include <cuda_runtime.h>
#include <cuda_fp16.h>
#include <math.h>
#include <stdint.h>

// ---------------- problem constants -----------------------------------------
#define TOKENS 4096
#define DDIM   1024
#define FDIM   4096
#define NEXP   8
#define PAIRS  (TOKENS * 2)
#define CAP    TOKENS

// ---------------- GEMM tiling ------------------------------------------------
#define BM 128
#define BN 128
#define BK 32
#define NTH 256                    // 8 warps, 2(m) x 4(n), warp tile 64x32
#define A_BYTES  (BM * 80)         // 10240 (LDT=40 halves, 80B rows)
#define B_BYTES  (BN * 80)         // 10240
#define SOFF_STAGE 1024
#define SOFF_B (SOFF_STAGE + 3 * A_BYTES)
#define SMEM_BYTES (SOFF_STAGE + 3 * A_BYTES + 3 * B_BYTES)   // 62464

// ---------------- scratch (72 MB — proven budget) -------------------------------
__device__ int    g_counts[NEXP];
__device__ int    g_list[NEXP * CAP];
__device__ float  g_prob[PAIRS];
__device__ __half g_xf[(size_t)TOKENS * DDIM];   // fp16 x  (8 MB)
__device__ __half g_hf[(size_t)PAIRS * FDIM];    // fp16 h  (64 MB)

// ---------------- ptx helpers --------------------------------------------------
__device__ __forceinline__ uint32_t smem_u32(const void* p) {
    uint32_t a;
    asm("{ .reg .u64 t; cvta.to.shared.u64 t, %1; cvt.u32.u64 %0, t; }"
        : "=r"(a) : "l"(p));
    return a;
}
__device__ __forceinline__ void cp16(uint32_t dst, const void* src) {
    asm volatile("cp.async.cg.shared.global [%0], [%1], 16;" :: "r"(dst), "l"(src));
}
__device__ __forceinline__ void cp_commit() {
    asm volatile("cp.async.commit_group;" ::: "memory");
}
template <int N>
__device__ __forceinline__ void cp_wait() {
    asm volatile("cp.async.wait_group %0;" :: "n"(N) : "memory");
}
__device__ __forceinline__ void ldm4(uint32_t* r, uint32_t a) {
    asm volatile("ldmatrix.sync.aligned.m8n8.x4.shared.b16 {%0,%1,%2,%3}, [%4];"
                 : "=r"(r[0]), "=r"(r[1]), "=r"(r[2]), "=r"(r[3]) : "r"(a));
}
__device__ __forceinline__ void mma_f16(float* c, const uint32_t* a, const uint32_t* b) {
    asm volatile(
        "mma.sync.aligned.m16n8k16.row.col.f32.f16.f16.f32 "
        "{%0,%1,%2,%3}, {%4,%5,%6,%7}, {%8,%9}, {%0,%1,%2,%3};"
        : "+f"(c[0]), "+f"(c[1]), "+f"(c[2]), "+f"(c[3])
        : "r"(a[0]), "r"(a[1]), "r"(a[2]), "r"(a[3]), "r"(b[0]), "r"(b[1]));
}

// ---------------- math helpers --------------------------------------------------
__device__ __forceinline__ float gelu_tanh(float v) {
    const float c = 0.7978845608028654f;
    float u = c * (v + 0.044715f * v * v * v);
    return 0.5f * v * (1.0f + tanhf(u));
}
// convert 8 fp32 (two float4) to 8 fp16 and store as one 16B STS
__device__ __forceinline__ void conv_sts16(char* smem, uint32_t off,
                                           float4 a, float4 b) {
    __half2 h0 = __halves2half2(__float2half_rn(a.x), __float2half_rn(a.y));
    __half2 h1 = __halves2half2(__float2half_rn(a.z), __float2half_rn(a.w));
    __half2 h2 = __halves2half2(__float2half_rn(b.x), __float2half_rn(b.y));
    __half2 h3 = __halves2half2(__float2half_rn(b.z), __float2half_rn(b.w));
    uint4 v = make_uint4(*(uint32_t*)&h0, *(uint32_t*)&h1,
                         *(uint32_t*)&h2, *(uint32_t*)&h3);
    *reinterpret_cast<uint4*>(smem + off) = v;
}

// ---------------- kernel 0: zero counts (8 ints only) ----------------------------
__global__ void init_counts_kernel() {
    if (threadIdx.x < NEXP) g_counts[threadIdx.x] = 0;
}

// ---------------- kernel: gate + x->fp16 convert + out-zero (fused) --------------
__global__ __launch_bounds__(256) void gate_kernel(
    const float* __restrict__ x, const float* __restrict__ gw,
    float* __restrict__ out)
{
    int t = blockIdx.x;
    const float* xr = x + (size_t)t * DDIM;

    // zero this token's output row (stream order puts this before layer-2 atomics)
    {
        float4 z = make_float4(0.f, 0.f, 0.f, 0.f);
        float4* orow = (float4*)(out + (size_t)t * DDIM);
        orow[threadIdx.x] = z;                 // 256 x 16B = 4096B... DDIM*4B=4096B
    }

    float acc[NEXP];
#pragma unroll
    for (int e = 0; e < NEXP; e++) acc[e] = 0.0f;
    for (int d = threadIdx.x; d < DDIM; d += 256) {
        float xv = xr[d];
        g_xf[(size_t)t * DDIM + d] = __float2half_rn(xv);
#pragma unroll
        for (int e = 0; e < NEXP; e++) acc[e] += xv * gw[e * DDIM + d];
    }
#pragma unroll
    for (int e = 0; e < NEXP; e++) {
#pragma unroll
        for (int o = 16; o > 0; o >>= 1)
            acc[e] += __shfl_xor_sync(0xffffffff, acc[e], o);
    }
    __shared__ float red[NEXP][8];
    int warp = threadIdx.x >> 5, lane = threadIdx.x & 31;
    if (lane == 0) {
#pragma unroll
        for (int e = 0; e < NEXP; e++) red[e][warp] = acc[e];
    }
    __syncthreads();
    if (threadIdx.x == 0) {
        float lg[NEXP];
#pragma unroll
        for (int e = 0; e < NEXP; e++) {
            float s = 0.0f;
#pragma unroll
            for (int w = 0; w < 8; w++) s += red[e][w];
            lg[e] = s;
        }
        float mx = lg[0];
#pragma unroll
        for (int e = 1; e < NEXP; e++) mx = fmaxf(mx, lg[e]);
        float pe[NEXP], s = 0.0f;
#pragma unroll
        for (int e = 0; e < NEXP; e++) { pe[e] = expf(lg[e] - mx); s += pe[e]; }
        float inv = 1.0f / s;
        int i0 = 0;
#pragma unroll
        for (int e = 1; e < NEXP; e++) if (pe[e] > pe[i0]) i0 = e;
        int i1 = (i0 == 0) ? 1 : 0;
#pragma unroll
        for (int e = 0; e < NEXP; e++)
            if (e != i0 && pe[e] > pe[i1]) i1 = e;
        int p0 = t * 2, p1 = t * 2 + 1;
        g_prob[p0] = pe[i0] * inv;
        g_prob[p1] = pe[i1] * inv;
        int pos0 = atomicAdd(&g_counts[i0], 1);
        g_list[i0 * CAP + pos0] = p0;
        int pos1 = atomicAdd(&g_counts[i1], 1);
        g_list[i1 * CAP + pos1] = p1;
    }
}

// ---------------- grouped fp16 GEMM (R15 mainloop, 16B W-STS) --------------------
template <int KDIM, bool L2TAG>
__global__ __launch_bounds__(NTH, 2)
void moe_fp16(const float* __restrict__ W,
              const float* __restrict__ bias,
              float* __restrict__ dout)
{
    constexpr int KSPLIT = L2TAG ? 2 : 1;
    constexpr int KLOC = KDIM / KSPLIT;
    constexpr int NCH = KLOC / BK;

    int e   = blockIdx.z;
    int cnt = g_counts[e];
    int m0  = blockIdx.y * BM;
    if (m0 >= cnt) return;
    int ks    = blockIdx.x % KSPLIT;
    int n0    = (blockIdx.x / KSPLIT) * BN;
    int kbase = ks * KLOC;

    extern __shared__ __align__(128) char smem[];
    uint32_t sb = smem_u32(smem);
    int* rows = (int*)smem;

    int tid = threadIdx.x, wid = tid >> 5, lane = tid & 31;

    if (tid < BM) {
        int m = m0 + tid;
        rows[tid] = g_list[e * CAP + (m < cnt ? m : m0)];
    }
    __syncthreads();

    // ---- A: cp.async mapping (2 threads/row, 32B each) ----
    int arow = tid >> 1;
    int pa = rows[arow];
    const __half* a_rowp = L2TAG ? (g_hf + (size_t)pa * KDIM)
                                 : (g_xf + (size_t)(pa >> 1) * KDIM);
    const char* a_src = (const char*)(a_rowp + kbase) + (tid & 1) * 32;
    uint32_t a_dst = sb + SOFF_STAGE + (uint32_t)arow * 80 + (tid & 1) * 32;

    // ---- W: 4 threads/row, 8 floats each -> 2 LDG.128 + 1 STS.128 --------------
    const float* wp[2];
    uint32_t woff[2];
#pragma unroll
    for (int j = 0; j < 2; j++) {
        int s = tid + j * 256;                 // 512 slots = 128 rows x 4
        int r = s >> 2;
        int k8 = (s & 3) << 3;                 // float offset: 0,8,16,24
        wp[j] = W + ((size_t)(n0 + r) * NEXP + e) * KDIM + kbase + k8;
        woff[j] = (uint32_t)r * 80 + (uint32_t)k8 * 2;
    }

    // ---- fragment addressing (validated R2/R5/R6/R8/R15; LDT=40) ----
    int wm = wid & 1, wn = wid >> 1;
    int li = lane >> 3, lr = lane & 7;
    uint32_t aoff = (uint32_t)((wm * 64 + lr + (li & 1) * 8) * 80 + (li >> 1) * 16);
    uint32_t boff = (uint32_t)((wn * 32 + (li >> 1) * 8 + lr) * 80 + (li & 1) * 16);

    float acc[4][4][4];
#pragma unroll
    for (int im = 0; im < 4; im++)
#pragma unroll
        for (int in = 0; in < 4; in++)
#pragma unroll
            for (int q = 0; q < 4; q++) acc[im][in][q] = 0.0f;

    // ---- prologue ----
    cp16(a_dst, a_src);
    cp16(a_dst + 16, a_src + 16);
    cp_commit();
    cp16(a_dst + A_BYTES, a_src + BK * 2);
    cp16(a_dst + A_BYTES + 16, a_src + BK * 2 + 16);
    cp_commit();
    float4 wreg[2][2];
#pragma unroll
    for (int j = 0; j < 2; j++) {
        wreg[j][0] = *(const float4*)(wp[j]);
        wreg[j][1] = *(const float4*)(wp[j] + 4);
    }
    char* b0c = smem + SOFF_B;
#pragma unroll
    for (int j = 0; j < 2; j++)
        conv_sts16(b0c, woff[j], wreg[j][0], wreg[j][1]);
#pragma unroll
    for (int j = 0; j < 2; j++) {
        wreg[j][0] = *(const float4*)(wp[j] + BK);
        wreg[j][1] = *(const float4*)(wp[j] + BK + 4);
    }

    int sA = 0, sB = 0;        // both track i % 3
    for (int i = 0; i < NCH; i++) {
        cp_wait<1>();          // A(i) landed; A(i+1) may still fly
        __syncthreads();       // compute(i-1) fully done -> buffers reusable

        // issue A(i+2) into buffer (i+2)%3
        if (i + 2 < NCH) {
            int s2 = sA + 2; if (s2 >= 3) s2 -= 3;
            uint32_t off = (uint32_t)s2 * A_BYTES;
            int kb = (i + 2) * BK * 2;
            cp16(a_dst + off, a_src + kb);
            cp16(a_dst + off + 16, a_src + kb + 16);
        }
        cp_commit();

        uint32_t As = sb + SOFF_STAGE + (uint32_t)sA * A_BYTES;
        uint32_t Bs = sb + SOFF_B + (uint32_t)sB * B_BYTES;

        // preload B(k16#0) frags
        uint32_t bf[2][4][2];
        {
            uint32_t t4[4];
            ldm4(t4, Bs + boff);
            bf[0][0][0] = t4[0]; bf[0][0][1] = t4[1];
            bf[0][1][0] = t4[2]; bf[0][1][1] = t4[3];
            ldm4(t4, Bs + boff + 1280);
            bf[0][2][0] = t4[0]; bf[0][2][1] = t4[1];
            bf[0][3][0] = t4[2]; bf[0][3][1] = t4[3];
        }

        // hidden W stage: STS W(i+1) into B((i+1)%3); then LDG W(i+2)
        if (i + 1 < NCH) {
            int s1 = sB + 1; if (s1 >= 3) s1 -= 3;
            char* bc = smem + SOFF_B + (size_t)s1 * B_BYTES;
#pragma unroll
            for (int j = 0; j < 2; j++)
                conv_sts16(bc, woff[j], wreg[j][0], wreg[j][1]);
        }
        if (i + 2 < NCH) {
            int k0 = (i + 2) * BK;
#pragma unroll
            for (int j = 0; j < 2; j++) {
                wreg[j][0] = *(const float4*)(wp[j] + k0);
                wreg[j][1] = *(const float4*)(wp[j] + k0 + 4);
            }
        }

        // compute chunk i (2 k16 groups), B frags double-buffered
#pragma unroll
        for (int kk = 0; kk < BK; kk += 16) {
            int cur = (kk >> 4) & 1;
            if (kk + 16 < BK) {
                uint32_t t4[4];
                ldm4(t4, Bs + boff + (kk + 16) * 2);
                bf[cur ^ 1][0][0] = t4[0]; bf[cur ^ 1][0][1] = t4[1];
                bf[cur ^ 1][1][0] = t4[2]; bf[cur ^ 1][1][1] = t4[3];
                ldm4(t4, Bs + boff + 1280 + (kk + 16) * 2);
                bf[cur ^ 1][2][0] = t4[0]; bf[cur ^ 1][2][1] = t4[1];
                bf[cur ^ 1][3][0] = t4[2]; bf[cur ^ 1][3][1] = t4[3];
            }
#pragma unroll
            for (int im = 0; im < 4; im++) {
                uint32_t af[4];
                ldm4(af, As + aoff + im * 1280 + kk * 2);
#pragma unroll
                for (int in = 0; in < 4; in++)
                    mma_f16(acc[im][in], af, bf[cur][in]);
            }
        }
        if (++sA == 3) sA = 0;
        if (++sB == 3) sB = 0;
    }

    // ---- epilogue (R15 scattered-store form) ----
    int qr = lane >> 2, qc = (lane & 3) * 2;
#pragma unroll
    for (int im = 0; im < 4; im++) {
#pragma unroll
        for (int half = 0; half < 2; half++) {
            int m_loc = wm * 64 + im * 16 + qr + half * 8;
            if (m0 + m_loc >= cnt) continue;
            int p = rows[m_loc];
            if (!L2TAG) {
                __half* hp = g_hf + (size_t)p * FDIM;
                const float* bb = bias + (size_t)e * FDIM;
#pragma unroll
                for (int in = 0; in < 4; in++) {
                    int col = n0 + wn * 32 + in * 8 + qc;
                    float v0 = acc[im][in][half * 2 + 0] + bb[col];
                    float v1 = acc[im][in][half * 2 + 1] + bb[col + 1];
                    __half2 hv = __halves2half2(__float2half_rn(gelu_tanh(v0)),
                                                __float2half_rn(gelu_tanh(v1)));
                    *reinterpret_cast<uint32_t*>(hp + col) = *(uint32_t*)&hv;
                }
            } else {
                float pr = g_prob[p];
                float* op = dout + (size_t)(p >> 1) * DDIM;
                const float* bb = bias + (size_t)e * DDIM;
#pragma unroll
                for (int in = 0; in < 4; in++) {
                    int col = n0 + wn * 32 + in * 8 + qc;
                    float b0 = (ks == 0) ? bb[col] : 0.0f;
                    float b1 = (ks == 0) ? bb[col + 1] : 0.0f;
                    atomicAdd(&op[col],
                              pr * (acc[im][in][half * 2 + 0] + b0));
                    atomicAdd(&op[col + 1],
                              pr * (acc[im][in][half * 2 + 1] + b1));
                }
            }
        }
    }
}

// ---------------- launch --------------------------------------------------------------
extern "C" void kernel_launch(void* const* d_in, const int* in_sizes, int n_in,
                              void* d_out, int out_size)
{
    (void)in_sizes; (void)n_in; (void)out_size;
    const float* x  = (const float*)d_in[0];
    const float* gw = (const float*)d_in[1];
    const float* w1 = (const float*)d_in[2];
    const float* b1 = (const float*)d_in[3];
    const float* w2 = (const float*)d_in[4];
    const float* b2 = (const float*)d_in[5];
    float* out = (float*)d_out;

    cudaFuncSetAttribute(moe_fp16<DDIM, false>,
                         cudaFuncAttributeMaxDynamicSharedMemorySize, SMEM_BYTES);
    cudaFuncSetAttribute(moe_fp16<FDIM, true>,
                         cudaFuncAttributeMaxDynamicSharedMemorySize, SMEM_BYTES);

    init_counts_kernel<<<1, 32>>>();
    gate_kernel<<<TOKENS, 256>>>(x, gw, out);

    dim3 g1(FDIM / BN, TOKENS / BM, NEXP);        // 32 x 32 x 8
    moe_fp16<DDIM, false><<<g1, NTH, SMEM_BYTES>>>(w1, b1, nullptr);

    dim3 g2((DDIM / BN) * 2, TOKENS / BM, NEXP);  // 16 x 32 x 8, k-split
    moe_fp16<FDIM, true><<<g2, NTH, SMEM_BYTES>>>(w2, b2, out);
}